// round 7
// baseline (speedup 1.0000x reference)
#include <cuda_runtime.h>
#include <math.h>

// Problem constants
#define N_TOK   2048
#define DIM     512
#define POOLSZ  65536
#define HIDDEN  256
#define CHID    128
#define KSEL    256
#define TOKCH   256            // tokens per score-chunk (scratch = 64 MB)
#define NCHUNK  (N_TOK / TOKCH)

// Device scratch (static globals; no runtime allocation)
__device__ float g_h[N_TOK * HIDDEN];          // 2 MB  : relu(x@Ws1+bs1)
__device__ float g_scores[TOKCH * POOLSZ];     // 64 MB : per-chunk score matrix
__device__ int   g_budget[N_TOK];
__device__ int   g_topidx[N_TOK * KSEL];       // 2 MB
__device__ float g_topw[N_TOK * KSEL];         // 2 MB

// ---------------------------------------------------------------------------
// Kernel 1: complexity net -> budget[token]
// 16 tokens per CTA, 128 threads (one per hidden unit of the 128-wide net).
// ---------------------------------------------------------------------------
__global__ void budget_kernel(const float* __restrict__ x,
                              const float* __restrict__ Wc1,
                              const float* __restrict__ bc1,
                              const float* __restrict__ Wc2,
                              const float* __restrict__ bc2) {
    __shared__ float xs[16][DIM];     // 32 KB
    __shared__ float red[16][CHID];   // 8 KB
    int tid = threadIdx.x;            // 0..127
    int t0  = blockIdx.x * 16;

    const float4* xsrc = (const float4*)(x + (size_t)t0 * DIM);
    float4* xdst = (float4*)&xs[0][0];
    for (int i = tid; i < 16 * DIM / 4; i += 128) xdst[i] = xsrc[i];
    __syncthreads();

    float acc[16];
#pragma unroll
    for (int m = 0; m < 16; m++) acc[m] = 0.f;

    for (int i = 0; i < DIM; i += 4) {
        float w0 = Wc1[(i + 0) * CHID + tid];
        float w1 = Wc1[(i + 1) * CHID + tid];
        float w2 = Wc1[(i + 2) * CHID + tid];
        float w3 = Wc1[(i + 3) * CHID + tid];
#pragma unroll
        for (int m = 0; m < 16; m++) {
            float4 xv = *(const float4*)&xs[m][i];
            acc[m] += xv.x * w0 + xv.y * w1 + xv.z * w2 + xv.w * w3;
        }
    }

    float b1  = bc1[tid];
    float wc2 = Wc2[tid];
#pragma unroll
    for (int m = 0; m < 16; m++) red[m][tid] = fmaxf(acc[m] + b1, 0.f) * wc2;
    __syncthreads();

    if (tid < 16) {
        float s = bc2[0];
        for (int t = 0; t < CHID; t++) s += red[tid][t];
        float sig   = 1.f / (1.f + expf(-s));
        float scale = sig * sig;                       // complexity^2.0
        float raw   = 100.f + 156.f * scale;           // KMIN + (KMAX-KMIN)*scale
        raw = fminf(fmaxf(raw, 100.f), 256.f);
        g_budget[t0 + tid] = (int)rintf(raw);          // round-half-even like jnp.round
    }
}

// ---------------------------------------------------------------------------
// Kernel 2: scorer hidden h = relu(x @ Ws1 + bs1)   [2048, 256]
// 16 tokens per CTA, 256 threads (one per hidden unit). Ws1 value reused 16x.
// ---------------------------------------------------------------------------
__global__ void hidden_kernel(const float* __restrict__ x,
                              const float* __restrict__ Ws1,
                              const float* __restrict__ bs1) {
    __shared__ float xs[16][DIM];     // 32 KB
    int tid = threadIdx.x;            // 0..255
    int t0  = blockIdx.x * 16;

    const float4* xsrc = (const float4*)(x + (size_t)t0 * DIM);
    float4* xdst = (float4*)&xs[0][0];
    for (int i = tid; i < 16 * DIM / 4; i += 256) xdst[i] = xsrc[i];
    __syncthreads();

    float acc[16];
#pragma unroll
    for (int m = 0; m < 16; m++) acc[m] = 0.f;

    for (int i = 0; i < DIM; i += 4) {
        float w0 = Ws1[(i + 0) * HIDDEN + tid];
        float w1 = Ws1[(i + 1) * HIDDEN + tid];
        float w2 = Ws1[(i + 2) * HIDDEN + tid];
        float w3 = Ws1[(i + 3) * HIDDEN + tid];
#pragma unroll
        for (int m = 0; m < 16; m++) {
            float4 xv = *(const float4*)&xs[m][i];
            acc[m] += xv.x * w0 + xv.y * w1 + xv.z * w2 + xv.w * w3;
        }
    }

    float b = bs1[tid];
#pragma unroll
    for (int m = 0; m < 16; m++)
        g_h[(size_t)(t0 + m) * HIDDEN + tid] = fmaxf(acc[m] + b, 0.f);
}

// ---------------------------------------------------------------------------
// Kernel 3: chunk score GEMM  g_scores = g_h[t0:t0+256] @ Ws2 + bs2
// Classic 128x128 fp32 SGEMM tile, BK=16, 256 threads, 8x8 per thread.
// ---------------------------------------------------------------------------
__global__ void gemm_kernel(const float* __restrict__ Ws2,
                            const float* __restrict__ bs2,
                            int t0) {
    __shared__ float As[16][128];
    __shared__ float Bs[16][128];
    int tid = threadIdx.x;            // 0..255
    int tx = tid & 15;                // n group
    int ty = tid >> 4;                // m group
    int m0 = blockIdx.y * 128;        // chunk-local token offset
    int n0 = blockIdx.x * 128;        // pool-column offset

    float acc[8][8];
#pragma unroll
    for (int i = 0; i < 8; i++)
#pragma unroll
        for (int j = 0; j < 8; j++) acc[i][j] = 0.f;

    for (int k0 = 0; k0 < HIDDEN; k0 += 16) {
        // load A tile (128 tokens x 16 k), transposed into As[k][m]
        {
            int m  = tid >> 1;
            int kk = (tid & 1) * 8;
            const float* src = g_h + (size_t)(t0 + m0 + m) * HIDDEN + k0 + kk;
            float4 v0 = *(const float4*)src;
            float4 v1 = *(const float4*)(src + 4);
            As[kk + 0][m] = v0.x; As[kk + 1][m] = v0.y;
            As[kk + 2][m] = v0.z; As[kk + 3][m] = v0.w;
            As[kk + 4][m] = v1.x; As[kk + 5][m] = v1.y;
            As[kk + 6][m] = v1.z; As[kk + 7][m] = v1.w;
        }
        // load B tile (16 k x 128 n), coalesced float4
#pragma unroll
        for (int r = 0; r < 2; r++) {
            int s  = tid + r * 256;       // 0..511 float4 slots
            int kk = s >> 5;
            int nn = (s & 31) * 4;
            *(float4*)&Bs[kk][nn] =
                *(const float4*)(Ws2 + (size_t)(k0 + kk) * POOLSZ + n0 + nn);
        }
        __syncthreads();

#pragma unroll
        for (int kk = 0; kk < 16; kk++) {
            float4 a0 = *(const float4*)&As[kk][ty * 8];
            float4 a1 = *(const float4*)&As[kk][ty * 8 + 4];
            float4 b0 = *(const float4*)&Bs[kk][tx * 8];
            float4 b1 = *(const float4*)&Bs[kk][tx * 8 + 4];
            float a[8] = {a0.x, a0.y, a0.z, a0.w, a1.x, a1.y, a1.z, a1.w};
            float b[8] = {b0.x, b0.y, b0.z, b0.w, b1.x, b1.y, b1.z, b1.w};
#pragma unroll
            for (int i = 0; i < 8; i++)
#pragma unroll
                for (int j = 0; j < 8; j++) acc[i][j] += a[i] * b[j];
        }
        __syncthreads();
    }

    // epilogue: + bias, store to chunk scratch
    float bb[8];
#pragma unroll
    for (int j = 0; j < 8; j++) bb[j] = bs2[n0 + tx * 8 + j];
#pragma unroll
    for (int i = 0; i < 8; i++) {
        int m = m0 + ty * 8 + i;
        float4 o0 = make_float4(acc[i][0] + bb[0], acc[i][1] + bb[1],
                                acc[i][2] + bb[2], acc[i][3] + bb[3]);
        float4 o1 = make_float4(acc[i][4] + bb[4], acc[i][5] + bb[5],
                                acc[i][6] + bb[6], acc[i][7] + bb[7]);
        float* dst = &g_scores[(size_t)m * POOLSZ + n0 + tx * 8];
        *(float4*)dst       = o0;
        *(float4*)(dst + 4) = o1;
    }
}

// ---------------------------------------------------------------------------
// Kernel 4: per-token exact top-256 + softmax + budget mask
// 13-bit histogram radix-select -> candidate collect -> 1024-wide bitonic sort.
// ---------------------------------------------------------------------------
#define HBITS 13
#define HBINS 8192
#define CAND  1024

__device__ __forceinline__ unsigned f2key(float s) {
    unsigned u = __float_as_uint(s);
    return (u & 0x80000000u) ? ~u : (u | 0x80000000u);
}
__device__ __forceinline__ float key2f(unsigned k) {
    return (k & 0x80000000u) ? __uint_as_float(k ^ 0x80000000u)
                             : __uint_as_float(~k);
}

__global__ void topk_kernel(int t0) {
    __shared__ unsigned hist[HBINS];      // 32 KB
    __shared__ unsigned ckey[CAND];       // 4 KB
    __shared__ int      cidx[CAND];       // 4 KB
    __shared__ unsigned blocksum[256];
    __shared__ float    red[256];
    __shared__ unsigned s_thresh;
    __shared__ unsigned s_count;

    int tid  = threadIdx.x;               // 0..255
    int tloc = blockIdx.x;
    int tok  = t0 + tloc;
    const float* S = g_scores + (size_t)tloc * POOLSZ;

    for (int i = tid; i < HBINS; i += 256) hist[i] = 0;
    if (tid == 0) s_count = 0;
    __syncthreads();

    // pass 1: histogram of top 13 key bits
    for (int i = tid; i < POOLSZ; i += 256)
        atomicAdd(&hist[f2key(S[i]) >> (32 - HBITS)], 1u);
    __syncthreads();

    // suffix scan to find the bin containing the 256th-largest key
    unsigned local = 0;
    int base = tid * (HBINS / 256);
#pragma unroll
    for (int b = 0; b < HBINS / 256; b++) local += hist[base + b];
    blocksum[tid] = local;
    __syncthreads();
    if (tid == 0) {
        unsigned cum = 0;
        int blk = 255;
        for (; blk > 0; blk--) {
            if (cum + blocksum[blk] >= KSEL) break;
            cum += blocksum[blk];
        }
        int b = blk * (HBINS / 256) + (HBINS / 256) - 1;
        for (;; b--) {
            unsigned c = hist[b];
            if (cum + c >= KSEL || b == 0) break;
            cum += c;
        }
        s_thresh = (unsigned)b << (32 - HBITS);
    }
    __syncthreads();
    unsigned thresh = s_thresh;

    // pass 2: collect candidates (all keys >= threshold-bin floor; count >= 256)
    for (int i = tid; i < POOLSZ; i += 256) {
        unsigned key = f2key(S[i]);
        if (key >= thresh) {
            unsigned pos = atomicAdd(&s_count, 1u);
            if (pos < CAND) { ckey[pos] = key; cidx[pos] = i; }
        }
    }
    __syncthreads();
    unsigned cnt = s_count; if (cnt > CAND) cnt = CAND;
    for (int i = tid; i < CAND; i += 256)
        if (i >= (int)cnt) { ckey[i] = 0; cidx[i] = 0; }
    __syncthreads();

    // bitonic sort ascending (largest ends at index CAND-1)
    for (unsigned k = 2; k <= CAND; k <<= 1) {
        for (unsigned j = k >> 1; j > 0; j >>= 1) {
            for (unsigned i = tid; i < CAND; i += 256) {
                unsigned ixj = i ^ j;
                if (ixj > i) {
                    bool up = ((i & k) == 0);
                    unsigned a = ckey[i], b = ckey[ixj];
                    bool sw = up ? (a > b) : (a < b);
                    if (sw) {
                        ckey[i] = b; ckey[ixj] = a;
                        int t = cidx[i]; cidx[i] = cidx[ixj]; cidx[ixj] = t;
                    }
                }
            }
            __syncthreads();
        }
    }

    // softmax over top-256, mask ranks >= budget
    int bud = g_budget[tok];
    float smax = key2f(ckey[CAND - 1]);
    int r = tid;                              // rank 0..255 (0 = largest)
    int e = CAND - 1 - r;
    float sr = key2f(ckey[e]);
    float ex = expf(sr - smax);
    red[tid] = ex;
    __syncthreads();
    for (int s = 128; s > 0; s >>= 1) {
        if (tid < s) red[tid] += red[tid + s];
        __syncthreads();
    }
    float w = ex / red[0];
    if (r >= bud) w = 0.f;
    g_topidx[(size_t)tok * KSEL + r] = cidx[e];
    g_topw[(size_t)tok * KSEL + r]   = w;
}

// ---------------------------------------------------------------------------
// Kernel 5: executor. One CTA per token, 8 warps; each warp handles 32 of the
// 256 selected rows, holding the gathered pool row in registers for both the
// dot product and the weighted accumulation. Masked (w==0) rows skipped.
// ---------------------------------------------------------------------------
__global__ void executor_kernel(const float* __restrict__ x,
                                const float* __restrict__ pool,
                                float* __restrict__ out) {
    __shared__ float xs[DIM];            // 2 KB
    __shared__ float partial[8][DIM];    // 16 KB
    int tok  = blockIdx.x;
    int tid  = threadIdx.x;              // 0..255
    int warp = tid >> 5;
    int lane = tid & 31;

    for (int i = tid; i < DIM; i += 256) xs[i] = x[(size_t)tok * DIM + i];
    __syncthreads();

    float acc[16];
#pragma unroll
    for (int j = 0; j < 16; j++) acc[j] = 0.f;

    for (int k = warp; k < KSEL; k += 8) {
        float w = g_topw[(size_t)tok * KSEL + k];
        if (w != 0.f) {
            int idx = g_topidx[(size_t)tok * KSEL + k];
            const float* row = pool + (size_t)idx * DIM;
            float r[16];
            float p = 0.f;
#pragma unroll
            for (int j = 0; j < 16; j++) {
                r[j] = row[lane + 32 * j];
                p += xs[lane + 32 * j] * r[j];
            }
#pragma unroll
            for (int off = 16; off > 0; off >>= 1)
                p += __shfl_xor_sync(0xffffffffu, p, off);
            float act = tanhf(p) * w;
#pragma unroll
            for (int j = 0; j < 16; j++) acc[j] += act * r[j];
        }
    }

#pragma unroll
    for (int j = 0; j < 16; j++) partial[warp][lane + 32 * j] = acc[j];
    __syncthreads();

    for (int e = tid; e < DIM; e += 256) {
        float s = xs[e];
#pragma unroll
        for (int wp = 0; wp < 8; wp++) s += partial[wp][e];
        out[(size_t)tok * DIM + e] = s;
    }
}

// ---------------------------------------------------------------------------
extern "C" void kernel_launch(void* const* d_in, const int* in_sizes, int n_in,
                              void* d_out, int out_size) {
    const float* x    = (const float*)d_in[0];
    const float* pool = (const float*)d_in[1];
    const float* Wc1  = (const float*)d_in[2];
    const float* bc1  = (const float*)d_in[3];
    const float* Wc2  = (const float*)d_in[4];
    const float* bc2  = (const float*)d_in[5];
    const float* Ws1  = (const float*)d_in[6];
    const float* bs1  = (const float*)d_in[7];
    const float* Ws2  = (const float*)d_in[8];
    const float* bs2  = (const float*)d_in[9];
    float* out = (float*)d_out;

    budget_kernel<<<N_TOK / 16, 128>>>(x, Wc1, bc1, Wc2, bc2);
    hidden_kernel<<<N_TOK / 16, 256>>>(x, Ws1, bs1);

    for (int c = 0; c < NCHUNK; c++) {
        int t0 = c * TOKCH;
        dim3 g(POOLSZ / 128, TOKCH / 128);
        gemm_kernel<<<g, 256>>>(Ws2, bs2, t0);
        topk_kernel<<<TOKCH, 256>>>(t0);
    }

    executor_kernel<<<N_TOK, 256>>>(x, pool, out);
}

// round 8
// speedup vs baseline: 2.4035x; 2.4035x over previous
#include <cuda_runtime.h>
#include <math.h>
#include <stdint.h>

// Problem constants
#define N_TOK   2048
#define DIM     512
#define POOLSZ  65536
#define HIDDEN  256
#define CHID    128
#define KSEL    256

// Device scratch (static globals; no runtime allocation)
__device__ float g_h[N_TOK * HIDDEN];                 // 2 MB
__device__ float g_scores[(size_t)N_TOK * POOLSZ];    // 512 MB full score matrix
__device__ int   g_budget[N_TOK];
__device__ int   g_topidx[N_TOK * KSEL];
__device__ float g_topw[N_TOK * KSEL];

// ---------------------------------------------------------------------------
// Kernel 1: complexity net -> budget[token]
// ---------------------------------------------------------------------------
__global__ void budget_kernel(const float* __restrict__ x,
                              const float* __restrict__ Wc1,
                              const float* __restrict__ bc1,
                              const float* __restrict__ Wc2,
                              const float* __restrict__ bc2) {
    __shared__ float xs[16][DIM];
    __shared__ float red[16][CHID];
    int tid = threadIdx.x;            // 0..127
    int t0  = blockIdx.x * 16;

    const float4* xsrc = (const float4*)(x + (size_t)t0 * DIM);
    float4* xdst = (float4*)&xs[0][0];
    for (int i = tid; i < 16 * DIM / 4; i += 128) xdst[i] = xsrc[i];
    __syncthreads();

    float acc[16];
#pragma unroll
    for (int m = 0; m < 16; m++) acc[m] = 0.f;

    for (int i = 0; i < DIM; i += 4) {
        float w0 = Wc1[(i + 0) * CHID + tid];
        float w1 = Wc1[(i + 1) * CHID + tid];
        float w2 = Wc1[(i + 2) * CHID + tid];
        float w3 = Wc1[(i + 3) * CHID + tid];
#pragma unroll
        for (int m = 0; m < 16; m++) {
            float4 xv = *(const float4*)&xs[m][i];
            acc[m] += xv.x * w0 + xv.y * w1 + xv.z * w2 + xv.w * w3;
        }
    }

    float b1  = bc1[tid];
    float wc2 = Wc2[tid];
#pragma unroll
    for (int m = 0; m < 16; m++) red[m][tid] = fmaxf(acc[m] + b1, 0.f) * wc2;
    __syncthreads();

    if (tid < 16) {
        float s = bc2[0];
        for (int t = 0; t < CHID; t++) s += red[tid][t];
        float sig   = 1.f / (1.f + expf(-s));
        float scale = sig * sig;
        float raw   = 100.f + 156.f * scale;
        raw = fminf(fmaxf(raw, 100.f), 256.f);
        g_budget[t0 + tid] = (int)rintf(raw);
    }
}

// ---------------------------------------------------------------------------
// Kernel 2: scorer hidden h = relu(x @ Ws1 + bs1)
// ---------------------------------------------------------------------------
__global__ void hidden_kernel(const float* __restrict__ x,
                              const float* __restrict__ Ws1,
                              const float* __restrict__ bs1) {
    __shared__ float xs[16][DIM];
    int tid = threadIdx.x;            // 0..255
    int t0  = blockIdx.x * 16;

    const float4* xsrc = (const float4*)(x + (size_t)t0 * DIM);
    float4* xdst = (float4*)&xs[0][0];
    for (int i = tid; i < 16 * DIM / 4; i += 256) xdst[i] = xsrc[i];
    __syncthreads();

    float acc[16];
#pragma unroll
    for (int m = 0; m < 16; m++) acc[m] = 0.f;

    for (int i = 0; i < DIM; i += 4) {
        float w0 = Ws1[(i + 0) * HIDDEN + tid];
        float w1 = Ws1[(i + 1) * HIDDEN + tid];
        float w2 = Ws1[(i + 2) * HIDDEN + tid];
        float w3 = Ws1[(i + 3) * HIDDEN + tid];
#pragma unroll
        for (int m = 0; m < 16; m++) {
            float4 xv = *(const float4*)&xs[m][i];
            acc[m] += xv.x * w0 + xv.y * w1 + xv.z * w2 + xv.w * w3;
        }
    }

    float b = bs1[tid];
#pragma unroll
    for (int m = 0; m < 16; m++)
        g_h[(size_t)(t0 + m) * HIDDEN + tid] = fmaxf(acc[m] + b, 0.f);
}

// ---------------------------------------------------------------------------
// Kernel 3: tf32 tensor-core GEMM  g_scores = g_h @ Ws2 + bs2
// CTA tile 128x128, BK=32, 8 warps (2m x 4n), warp tile 64x32,
// mma.sync.m16n8k8.tf32. Conflict-free smem layouts:
//   As[128][36]  (pad 36 => bank = 4*g + tg, injective)
//   Bs[32][132]  (pad 132 => bank = 4*k + n,  injective)
// grid = (16 m-tiles, 512 n-tiles): consecutive CTAs share the B slice in L2,
// so Ws2 (64 MB) is read from DRAM exactly once.
// ---------------------------------------------------------------------------
__device__ __forceinline__ uint32_t f2tf32(float f) {
    uint32_t r;
    asm("cvt.rna.tf32.f32 %0, %1;" : "=r"(r) : "f"(f));
    return r;
}

__global__ __launch_bounds__(256, 2) void gemm_kernel(const float* __restrict__ Ws2,
                                                      const float* __restrict__ bs2) {
    __shared__ float As[128][36];   // 18.4 KB
    __shared__ float Bs[32][132];   // 16.9 KB

    int tid  = threadIdx.x;
    int warp = tid >> 5, lane = tid & 31;
    int wm = warp >> 2, wn = warp & 3;      // 2 x 4 warp grid
    int g  = lane >> 2, tg = lane & 3;      // groupID, threadID-in-group
    int m0 = blockIdx.x * 128;
    int n0 = blockIdx.y * 128;

    float acc[4][4][4];
#pragma unroll
    for (int i = 0; i < 4; i++)
#pragma unroll
        for (int j = 0; j < 4; j++)
#pragma unroll
            for (int c = 0; c < 4; c++) acc[i][j][c] = 0.f;

    for (int kb = 0; kb < HIDDEN; kb += 32) {
        // stage A: 128 rows x 32 k  (tf32-converted), layout [m][k]
#pragma unroll
        for (int i = 0; i < 4; i++) {
            int s   = tid + i * 256;
            int row = s >> 3;
            int kq  = (s & 7) * 4;
            float4 v = *(const float4*)(g_h + (size_t)(m0 + row) * HIDDEN + kb + kq);
            float4 t;
            t.x = __uint_as_float(f2tf32(v.x));
            t.y = __uint_as_float(f2tf32(v.y));
            t.z = __uint_as_float(f2tf32(v.z));
            t.w = __uint_as_float(f2tf32(v.w));
            *(float4*)&As[row][kq] = t;
        }
        // stage B: 32 k x 128 n, layout [k][n]
#pragma unroll
        for (int i = 0; i < 4; i++) {
            int s  = tid + i * 256;
            int k  = s >> 5;
            int n4 = (s & 31) * 4;
            float4 v = *(const float4*)(Ws2 + (size_t)(kb + k) * POOLSZ + n0 + n4);
            float4 t;
            t.x = __uint_as_float(f2tf32(v.x));
            t.y = __uint_as_float(f2tf32(v.y));
            t.z = __uint_as_float(f2tf32(v.z));
            t.w = __uint_as_float(f2tf32(v.w));
            *(float4*)&Bs[k][n4] = t;
        }
        __syncthreads();

#pragma unroll
        for (int kk = 0; kk < 32; kk += 8) {
            uint32_t af[4][4];
#pragma unroll
            for (int mt = 0; mt < 4; mt++) {
                int m = wm * 64 + mt * 16;
                af[mt][0] = __float_as_uint(As[m + g][kk + tg]);
                af[mt][1] = __float_as_uint(As[m + g + 8][kk + tg]);
                af[mt][2] = __float_as_uint(As[m + g][kk + tg + 4]);
                af[mt][3] = __float_as_uint(As[m + g + 8][kk + tg + 4]);
            }
            uint32_t bf[4][2];
#pragma unroll
            for (int nt = 0; nt < 4; nt++) {
                int n = wn * 32 + nt * 8;
                bf[nt][0] = __float_as_uint(Bs[kk + tg][n + g]);
                bf[nt][1] = __float_as_uint(Bs[kk + tg + 4][n + g]);
            }
#pragma unroll
            for (int mt = 0; mt < 4; mt++)
#pragma unroll
                for (int nt = 0; nt < 4; nt++) {
                    asm volatile(
                        "mma.sync.aligned.m16n8k8.row.col.f32.tf32.tf32.f32 "
                        "{%0,%1,%2,%3}, {%4,%5,%6,%7}, {%8,%9}, {%0,%1,%2,%3};"
                        : "+f"(acc[mt][nt][0]), "+f"(acc[mt][nt][1]),
                          "+f"(acc[mt][nt][2]), "+f"(acc[mt][nt][3])
                        : "r"(af[mt][0]), "r"(af[mt][1]),
                          "r"(af[mt][2]), "r"(af[mt][3]),
                          "r"(bf[nt][0]), "r"(bf[nt][1]));
                }
        }
        __syncthreads();
    }

    // epilogue: + bias, store
#pragma unroll
    for (int nt = 0; nt < 4; nt++) {
        int n = n0 + wn * 32 + nt * 8 + 2 * tg;
        float2 bias = *(const float2*)(bs2 + n);
#pragma unroll
        for (int mt = 0; mt < 4; mt++) {
            int m = m0 + wm * 64 + mt * 16 + g;
            float2 o0 = make_float2(acc[mt][nt][0] + bias.x, acc[mt][nt][1] + bias.y);
            float2 o1 = make_float2(acc[mt][nt][2] + bias.x, acc[mt][nt][3] + bias.y);
            *(float2*)&g_scores[(size_t)m * POOLSZ + n]       = o0;
            *(float2*)&g_scores[(size_t)(m + 8) * POOLSZ + n] = o1;
        }
    }
}

// ---------------------------------------------------------------------------
// Kernel 4: per-token exact top-256 + softmax + budget mask. 512 threads,
// one CTA per token; float4 streaming; 13-bit histogram radix-select ->
// candidate collect -> 1024-wide bitonic sort.
// ---------------------------------------------------------------------------
#define HBITS 13
#define HBINS 8192
#define CAND  1024
#define TPBK  512

__device__ __forceinline__ unsigned f2key(float s) {
    unsigned u = __float_as_uint(s);
    return (u & 0x80000000u) ? ~u : (u | 0x80000000u);
}
__device__ __forceinline__ float key2f(unsigned k) {
    return (k & 0x80000000u) ? __uint_as_float(k ^ 0x80000000u)
                             : __uint_as_float(~k);
}

__global__ void topk_kernel() {
    __shared__ unsigned hist[HBINS];      // 32 KB
    __shared__ unsigned ckey[CAND];       // 4 KB
    __shared__ int      cidx[CAND];       // 4 KB
    __shared__ unsigned blocksum[TPBK];
    __shared__ float    red[256];
    __shared__ unsigned s_thresh;
    __shared__ unsigned s_count;

    int tid = threadIdx.x;                // 0..511
    int tok = blockIdx.x;
    const float4* S4 = (const float4*)(g_scores + (size_t)tok * POOLSZ);

    for (int i = tid; i < HBINS; i += TPBK) hist[i] = 0;
    if (tid == 0) s_count = 0;
    __syncthreads();

    // pass 1: histogram of top 13 key bits
    for (int i = tid; i < POOLSZ / 4; i += TPBK) {
        float4 v = S4[i];
        atomicAdd(&hist[f2key(v.x) >> (32 - HBITS)], 1u);
        atomicAdd(&hist[f2key(v.y) >> (32 - HBITS)], 1u);
        atomicAdd(&hist[f2key(v.z) >> (32 - HBITS)], 1u);
        atomicAdd(&hist[f2key(v.w) >> (32 - HBITS)], 1u);
    }
    __syncthreads();

    // suffix scan to locate the bin containing the 256th-largest key
    unsigned local = 0;
    int base = tid * (HBINS / TPBK);
#pragma unroll
    for (int b = 0; b < HBINS / TPBK; b++) local += hist[base + b];
    blocksum[tid] = local;
    __syncthreads();
    if (tid == 0) {
        unsigned cum = 0;
        int blk = TPBK - 1;
        for (; blk > 0; blk--) {
            if (cum + blocksum[blk] >= KSEL) break;
            cum += blocksum[blk];
        }
        int b = blk * (HBINS / TPBK) + (HBINS / TPBK) - 1;
        for (;; b--) {
            unsigned c = hist[b];
            if (cum + c >= KSEL || b == 0) break;
            cum += c;
        }
        s_thresh = (unsigned)b << (32 - HBITS);
    }
    __syncthreads();
    unsigned thresh = s_thresh;

    // pass 2: collect candidates
    for (int i = tid; i < POOLSZ / 4; i += TPBK) {
        float4 v = S4[i];
        float vv[4] = {v.x, v.y, v.z, v.w};
#pragma unroll
        for (int j = 0; j < 4; j++) {
            unsigned key = f2key(vv[j]);
            if (key >= thresh) {
                unsigned pos = atomicAdd(&s_count, 1u);
                if (pos < CAND) { ckey[pos] = key; cidx[pos] = i * 4 + j; }
            }
        }
    }
    __syncthreads();
    unsigned cnt = s_count; if (cnt > CAND) cnt = CAND;
    for (int i = tid; i < CAND; i += TPBK)
        if (i >= (int)cnt) { ckey[i] = 0; cidx[i] = 0; }
    __syncthreads();

    // bitonic sort ascending (largest ends at index CAND-1)
    for (unsigned k = 2; k <= CAND; k <<= 1) {
        for (unsigned j = k >> 1; j > 0; j >>= 1) {
            for (unsigned i = tid; i < CAND; i += TPBK) {
                unsigned ixj = i ^ j;
                if (ixj > i) {
                    bool up = ((i & k) == 0);
                    unsigned a = ckey[i], b = ckey[ixj];
                    bool sw = up ? (a > b) : (a < b);
                    if (sw) {
                        ckey[i] = b; ckey[ixj] = a;
                        int t = cidx[i]; cidx[i] = cidx[ixj]; cidx[ixj] = t;
                    }
                }
            }
            __syncthreads();
        }
    }

    // softmax over top-256, mask ranks >= budget
    int bud = g_budget[tok];
    float smax = key2f(ckey[CAND - 1]);
    float ex = 0.f;
    if (tid < 256) {
        int e = CAND - 1 - tid;
        ex = expf(key2f(ckey[e]) - smax);
        red[tid] = ex;
    }
    __syncthreads();
    for (int s = 128; s > 0; s >>= 1) {
        if (tid < s) red[tid] += red[tid + s];
        __syncthreads();
    }
    if (tid < 256) {
        int e = CAND - 1 - tid;
        float w = ex / red[0];
        if (tid >= bud) w = 0.f;
        g_topidx[(size_t)tok * KSEL + tid] = cidx[e];
        g_topw[(size_t)tok * KSEL + tid]   = w;
    }
}

// ---------------------------------------------------------------------------
// Kernel 5: executor. One CTA per token, 8 warps; each warp handles 32 of the
// 256 selected rows, holding the gathered pool row in registers.
// ---------------------------------------------------------------------------
__global__ void executor_kernel(const float* __restrict__ x,
                                const float* __restrict__ pool,
                                float* __restrict__ out) {
    __shared__ float xs[DIM];
    __shared__ float partial[8][DIM];
    int tok  = blockIdx.x;
    int tid  = threadIdx.x;
    int warp = tid >> 5;
    int lane = tid & 31;

    for (int i = tid; i < DIM; i += 256) xs[i] = x[(size_t)tok * DIM + i];
    __syncthreads();

    float acc[16];
#pragma unroll
    for (int j = 0; j < 16; j++) acc[j] = 0.f;

    for (int k = warp; k < KSEL; k += 8) {
        float w = g_topw[(size_t)tok * KSEL + k];
        if (w != 0.f) {
            int idx = g_topidx[(size_t)tok * KSEL + k];
            const float* row = pool + (size_t)idx * DIM;
            float r[16];
            float p = 0.f;
#pragma unroll
            for (int j = 0; j < 16; j++) {
                r[j] = __ldg(row + lane + 32 * j);
                p += xs[lane + 32 * j] * r[j];
            }
#pragma unroll
            for (int off = 16; off > 0; off >>= 1)
                p += __shfl_xor_sync(0xffffffffu, p, off);
            float act = tanhf(p) * w;
#pragma unroll
            for (int j = 0; j < 16; j++) acc[j] += act * r[j];
        }
    }

#pragma unroll
    for (int j = 0; j < 16; j++) partial[warp][lane + 32 * j] = acc[j];
    __syncthreads();

    for (int e = tid; e < DIM; e += 256) {
        float s = xs[e];
#pragma unroll
        for (int wp = 0; wp < 8; wp++) s += partial[wp][e];
        out[(size_t)tok * DIM + e] = s;
    }
}

// ---------------------------------------------------------------------------
extern "C" void kernel_launch(void* const* d_in, const int* in_sizes, int n_in,
                              void* d_out, int out_size) {
    const float* x    = (const float*)d_in[0];
    const float* pool = (const float*)d_in[1];
    const float* Wc1  = (const float*)d_in[2];
    const float* bc1  = (const float*)d_in[3];
    const float* Wc2  = (const float*)d_in[4];
    const float* bc2  = (const float*)d_in[5];
    const float* Ws1  = (const float*)d_in[6];
    const float* bs1  = (const float*)d_in[7];
    const float* Ws2  = (const float*)d_in[8];
    const float* bs2  = (const float*)d_in[9];
    float* out = (float*)d_out;

    budget_kernel<<<N_TOK / 16, 128>>>(x, Wc1, bc1, Wc2, bc2);
    hidden_kernel<<<N_TOK / 16, 256>>>(x, Ws1, bs1);

    dim3 ggrid(N_TOK / 128, POOLSZ / 128);   // x = m (fast) -> B reuse in L2
    gemm_kernel<<<ggrid, 256>>>(Ws2, bs2);

    topk_kernel<<<N_TOK, TPBK>>>();

    executor_kernel<<<N_TOK, 256>>>(x, pool, out);
}